// round 7
// baseline (speedup 1.0000x reference)
#include <cuda_runtime.h>
#include <cuda_fp16.h>
#include <math.h>

#define N_  4
#define L_  2048
#define D_  512
#define H_  8
#define DK_ 64
#define M_  (N_ * L_)

// Scratch (device globals: no allocation allowed in kernel_launch)
__device__ __half g_xqh[(size_t)M_ * D_];
__device__ __half g_xkh[(size_t)M_ * D_];
__device__ __half g_xvh[(size_t)M_ * D_];
__device__ __half g_wqh[(size_t)D_ * D_];
__device__ __half g_wkh[(size_t)D_ * D_];
__device__ __half g_wvh[(size_t)D_ * D_];
__device__ __half g_woh[(size_t)D_ * D_];
__device__ __half g_Qh[(size_t)M_ * D_];
__device__ __half g_Kh[(size_t)M_ * D_];
__device__ __half g_Vh[(size_t)M_ * D_];
__device__ __half g_Oh[(size_t)M_ * D_];
__device__ int    g_len[N_];

// ---------------------------------------------------------------------------
__device__ __forceinline__ void mma16(float c[4], const unsigned a[4],
                                      unsigned b0, unsigned b1) {
    asm volatile(
        "mma.sync.aligned.m16n8k16.row.col.f32.f16.f16.f32 "
        "{%0,%1,%2,%3}, {%4,%5,%6,%7}, {%8,%9}, {%0,%1,%2,%3};\n"
        : "+f"(c[0]), "+f"(c[1]), "+f"(c[2]), "+f"(c[3])
        : "r"(a[0]), "r"(a[1]), "r"(a[2]), "r"(a[3]), "r"(b0), "r"(b1));
}

__device__ __forceinline__ unsigned smaddr(const void* p) {
    return (unsigned)__cvta_generic_to_shared(p);
}
#define LDM_X4(r0, r1, r2, r3, addr) \
    asm volatile("ldmatrix.sync.aligned.m8n8.x4.shared.b16 {%0,%1,%2,%3}, [%4];" \
        : "=r"(r0), "=r"(r1), "=r"(r2), "=r"(r3) : "r"(addr))
#define LDM_X4T(r0, r1, r2, r3, addr) \
    asm volatile("ldmatrix.sync.aligned.m8n8.x4.trans.shared.b16 {%0,%1,%2,%3}, [%4];" \
        : "=r"(r0), "=r"(r1), "=r"(r2), "=r"(r3) : "r"(addr))
#define CP16(sm, gm) asm volatile("cp.async.cg.shared.global [%0], [%1], 16;\n" :: "r"(sm), "l"(gm))
#define CP_COMMIT()  asm volatile("cp.async.commit_group;\n")
#define CP_WAIT(n)   asm volatile("cp.async.wait_group %0;\n" :: "n"(n))

__device__ __forceinline__ unsigned h2bits(float lo, float hi) {
    __half2 h = __floats2half2_rn(lo, hi);
    return *(unsigned*)&h;
}

// ---------------------------------------------------------------------------
// Batched float -> half converters
// ---------------------------------------------------------------------------
__global__ void cvt3_kernel(const float4* __restrict__ s0,
                            const float4* __restrict__ s1,
                            const float4* __restrict__ s2,
                            uint2* __restrict__ d0, uint2* __restrict__ d1,
                            uint2* __restrict__ d2, int n4) {
    int i = blockIdx.x * 256 + threadIdx.x;
    if (i >= n4) return;
    const float4* s = (blockIdx.y == 0) ? s0 : (blockIdx.y == 1) ? s1 : s2;
    uint2*       d = (blockIdx.y == 0) ? d0 : (blockIdx.y == 1) ? d1 : d2;
    float4 v = s[i];
    d[i] = make_uint2(h2bits(v.x, v.y), h2bits(v.z, v.w));
}

__global__ void cvt4_kernel(const float4* __restrict__ s0,
                            const float4* __restrict__ s1,
                            const float4* __restrict__ s2,
                            const float4* __restrict__ s3,
                            uint2* __restrict__ d0, uint2* __restrict__ d1,
                            uint2* __restrict__ d2, uint2* __restrict__ d3,
                            int n4) {
    int i = blockIdx.x * 256 + threadIdx.x;
    if (i >= n4) return;
    const float4* s = (blockIdx.y == 0) ? s0 : (blockIdx.y == 1) ? s1
                    : (blockIdx.y == 2) ? s2 : s3;
    uint2*       d = (blockIdx.y == 0) ? d0 : (blockIdx.y == 1) ? d1
                    : (blockIdx.y == 2) ? d2 : d3;
    float4 v = s[i];
    d[i] = make_uint2(h2bits(v.x, v.y), h2bits(v.z, v.w));
}

// ---------------------------------------------------------------------------
// lengths: len[n] = 1 + max{ j : padding_mask[n][j] != 0 }
// ---------------------------------------------------------------------------
__global__ void len_kernel(const int* __restrict__ pm) {
    __shared__ int red[8];
    int n = blockIdx.x;
    int best = 0;
    for (int j = threadIdx.x; j < L_; j += 256)
        if (pm[(size_t)n * L_ + j] != 0) best = max(best, j + 1);
    #pragma unroll
    for (int off = 16; off; off >>= 1)
        best = max(best, __shfl_xor_sync(0xffffffffu, best, off));
    if ((threadIdx.x & 31) == 0) red[threadIdx.x >> 5] = best;
    __syncthreads();
    if (threadIdx.x == 0) {
        int b = red[0];
        #pragma unroll
        for (int w = 1; w < 8; w++) b = max(b, red[w]);
        g_len[n] = b;
    }
}

// ---------------------------------------------------------------------------
// GEMM body: C[128x128 tile] = (A @ W^T + bias) * scale, fp16 mma,
// cp.async double-buffered chunks (K=64), register-pipelined fragments.
// ---------------------------------------------------------------------------
#define GST 72
#define GEMM_SMEM (2 * 2 * 128 * GST * (int)sizeof(__half))

__device__ __forceinline__ void gemm_body(
    const __half* __restrict__ A, const __half* __restrict__ W,
    const float* __restrict__ bias, void* __restrict__ Cout, float scale,
    int half_out)
{
    extern __shared__ __half gsm[];
    __half* As = gsm;                   // [2][128*GST]
    __half* Ws = gsm + 2 * 128 * GST;   // [2][128*GST]

    int tid  = threadIdx.x;
    int lane = tid & 31, warp = tid >> 5;
    int g = lane >> 2, t = lane & 3;
    int wm = warp & 1, wn = warp >> 1;
    int row0 = blockIdx.x * 128;
    int col0 = blockIdx.y * 128;

    int arow = ((lane >> 3) & 1) * 8 + (lane & 7);
    int acol = (lane >> 4) * 8;
    int brow = (lane >> 4) * 8 + (lane & 7);
    int bcol = ((lane >> 3) & 1) * 8;

    float c[4][4][4];
    #pragma unroll
    for (int mf = 0; mf < 4; mf++)
        #pragma unroll
        for (int nf = 0; nf < 4; nf++)
            #pragma unroll
            for (int i = 0; i < 4; i++) c[mf][nf][i] = 0.f;

    // prologue: stage chunk 0
    #pragma unroll
    for (int i = 0; i < 4; i++) {
        int idx = tid + i * 256;
        int r = idx >> 3, u = idx & 7;
        CP16(smaddr(&As[r * GST + u * 8]), A + (size_t)(row0 + r) * D_ + u * 8);
        CP16(smaddr(&Ws[r * GST + u * 8]), W + (size_t)(col0 + r) * D_ + u * 8);
    }
    CP_COMMIT();

    unsigned a[2][4][4], b[2][4][2];

    #pragma unroll 1
    for (int ch = 0; ch < 8; ch++) {
        int cur = ch & 1;
        if (ch < 7) {
            int k0 = (ch + 1) * 64;
            __half* Ad = As + (cur ^ 1) * 128 * GST;
            __half* Wd = Ws + (cur ^ 1) * 128 * GST;
            #pragma unroll
            for (int i = 0; i < 4; i++) {
                int idx = tid + i * 256;
                int r = idx >> 3, u = idx & 7;
                CP16(smaddr(&Ad[r * GST + u * 8]), A + (size_t)(row0 + r) * D_ + k0 + u * 8);
                CP16(smaddr(&Wd[r * GST + u * 8]), W + (size_t)(col0 + r) * D_ + k0 + u * 8);
            }
            CP_COMMIT();
            CP_WAIT(1);
        } else {
            CP_WAIT(0);
        }
        __syncthreads();

        const __half* Ab = As + cur * 128 * GST;
        const __half* Wb = Ws + cur * 128 * GST;

        // preload kk=0 fragments
        #pragma unroll
        for (int mf = 0; mf < 4; mf++) {
            unsigned addr = smaddr(&Ab[(wm * 64 + mf * 16 + arow) * GST + acol]);
            LDM_X4(a[0][mf][0], a[0][mf][1], a[0][mf][2], a[0][mf][3], addr);
        }
        #pragma unroll
        for (int np = 0; np < 2; np++) {
            unsigned addr = smaddr(&Wb[(wn * 32 + np * 16 + brow) * GST + bcol]);
            LDM_X4(b[0][2 * np][0], b[0][2 * np][1], b[0][2 * np + 1][0], b[0][2 * np + 1][1], addr);
        }

        #pragma unroll
        for (int kk = 0; kk < 4; kk++) {
            int fc = kk & 1;
            if (kk < 3) {   // prefetch next kk's fragments
                int kn = (kk + 1) * 16;
                #pragma unroll
                for (int mf = 0; mf < 4; mf++) {
                    unsigned addr = smaddr(&Ab[(wm * 64 + mf * 16 + arow) * GST + kn + acol]);
                    LDM_X4(a[fc ^ 1][mf][0], a[fc ^ 1][mf][1], a[fc ^ 1][mf][2], a[fc ^ 1][mf][3], addr);
                }
                #pragma unroll
                for (int np = 0; np < 2; np++) {
                    unsigned addr = smaddr(&Wb[(wn * 32 + np * 16 + brow) * GST + kn + bcol]);
                    LDM_X4(b[fc ^ 1][2 * np][0], b[fc ^ 1][2 * np][1],
                           b[fc ^ 1][2 * np + 1][0], b[fc ^ 1][2 * np + 1][1], addr);
                }
            }
            #pragma unroll
            for (int mf = 0; mf < 4; mf++)
                #pragma unroll
                for (int nf = 0; nf < 4; nf++)
                    mma16(c[mf][nf], a[fc][mf], b[fc][nf][0], b[fc][nf][1]);
        }
        __syncthreads();
    }

    // Epilogue
    #pragma unroll
    for (int mf = 0; mf < 4; mf++) {
        int r0 = row0 + wm * 64 + mf * 16 + g;
        #pragma unroll
        for (int nf = 0; nf < 4; nf++) {
            int cc = col0 + wn * 32 + nf * 8 + 2 * t;
            float b0 = bias[cc], b1 = bias[cc + 1];
            float v00 = (c[mf][nf][0] + b0) * scale;
            float v01 = (c[mf][nf][1] + b1) * scale;
            float v10 = (c[mf][nf][2] + b0) * scale;
            float v11 = (c[mf][nf][3] + b1) * scale;
            if (half_out) {
                __half* C = (__half*)Cout;
                *(unsigned*)(C + (size_t)r0 * D_ + cc)       = h2bits(v00, v01);
                *(unsigned*)(C + (size_t)(r0 + 8) * D_ + cc) = h2bits(v10, v11);
            } else {
                float* C = (float*)Cout;
                *(float2*)(C + (size_t)r0 * D_ + cc)       = make_float2(v00, v01);
                *(float2*)(C + (size_t)(r0 + 8) * D_ + cc) = make_float2(v10, v11);
            }
        }
    }
}

// Fused Q/K/V projection: blockIdx.z selects the operand set
__global__ __launch_bounds__(256, 2) void gemm_qkv(
    const __half* __restrict__ xq, const __half* __restrict__ xk,
    const __half* __restrict__ xv,
    const __half* __restrict__ wq, const __half* __restrict__ wk,
    const __half* __restrict__ wv,
    const float* __restrict__ bq, const float* __restrict__ bk,
    const float* __restrict__ bv,
    __half* __restrict__ Q, __half* __restrict__ K, __half* __restrict__ V)
{
    int z = blockIdx.z;
    const __half* A = (z == 0) ? xq : (z == 1) ? xk : xv;
    const __half* W = (z == 0) ? wq : (z == 1) ? wk : wv;
    const float* bias = (z == 0) ? bq : (z == 1) ? bk : bv;
    __half* C = (z == 0) ? Q : (z == 1) ? K : V;
    float scale = (z == 0) ? 0.125f : 1.0f;   // 1/sqrt(64)
    gemm_body(A, W, bias, C, scale, 1);
}

// Output projection (float out)
__global__ __launch_bounds__(256, 2) void gemm_o(
    const __half* __restrict__ A, const __half* __restrict__ W,
    const float* __restrict__ bias, float* __restrict__ C)
{
    gemm_body(A, W, bias, C, 1.0f, 0);
}

// ---------------------------------------------------------------------------
// Flash attention, fp16 mma. Block = (128 q-rows, head, batch), 8 warps.
// Heavy (high-q0) blocks launch first for causal load balance.
// ---------------------------------------------------------------------------
#define AST 72
#define ATTN_SMEM (4 * 64 * AST * (int)sizeof(__half))

__global__ __launch_bounds__(256) void attn_h(int dummy) {
    extern __shared__ __half asm_[];
    __half* Ks = asm_;                        // [2][64*AST]
    __half* Vs = asm_ + 2 * 64 * AST;         // [2][64*AST]

    int tid  = threadIdx.x;
    int lane = tid & 31, warp = tid >> 5;
    int g = lane >> 2, t = lane & 3;
    int q0 = ((int)gridDim.x - 1 - (int)blockIdx.x) * 128;  // heavy blocks first
    int h  = blockIdx.y;
    int n  = blockIdx.z;

    int row_w = q0 + warp * 16;

    const __half* Qg = g_Qh + (size_t)n * L_ * D_ + (size_t)row_w * D_ + h * DK_;
    const __half* Kg = g_Kh + (size_t)n * L_ * D_ + h * DK_;
    const __half* Vg = g_Vh + (size_t)n * L_ * D_ + h * DK_;

    int brow = (lane >> 4) * 8 + (lane & 7);
    int bcol = ((lane >> 3) & 1) * 8;
    int vrow = ((lane >> 3) & 1) * 8 + (lane & 7);
    int vcol = (lane >> 4) * 8;

    unsigned qa[4][4];
    #pragma unroll
    for (int kk = 0; kk < 4; kk++) {
        qa[kk][0] = *(const unsigned*)&Qg[(size_t)g * D_       + kk * 16 + 2 * t];
        qa[kk][1] = *(const unsigned*)&Qg[(size_t)(g + 8) * D_ + kk * 16 + 2 * t];
        qa[kk][2] = *(const unsigned*)&Qg[(size_t)g * D_       + kk * 16 + 2 * t + 8];
        qa[kk][3] = *(const unsigned*)&Qg[(size_t)(g + 8) * D_ + kk * 16 + 2 * t + 8];
    }

    float oc[8][4];
    #pragma unroll
    for (int nf = 0; nf < 8; nf++)
        #pragma unroll
        for (int i = 0; i < 4; i++) oc[nf][i] = 0.f;

    float m0 = -1e30f, m1 = -1e30f, l0 = 0.f, l1 = 0.f;
    int r0 = row_w + g;
    int r1 = r0 + 8;
    int rmax_w = row_w + 15;

    int len   = g_len[n];
    int jend  = min(q0 + 128, len);
    int tiles = (jend + 63) >> 6;

    // prologue: tile 0 (K, V)
    {
        #pragma unroll
        for (int i = 0; i < 2; i++) {
            int idx = tid + i * 256;
            int r = idx >> 3, u = idx & 7;
            CP16(smaddr(&Ks[r * AST + u * 8]), Kg + (size_t)r * D_ + u * 8);
            CP16(smaddr(&Vs[r * AST + u * 8]), Vg + (size_t)r * D_ + u * 8);
        }
        CP_COMMIT();
    }

    #pragma unroll 1
    for (int it = 0; it < tiles; it++) {
        int cur = it & 1;
        int j0  = it * 64;
        if (it + 1 < tiles) {
            int jn = j0 + 64;
            __half* Kd = Ks + (cur ^ 1) * 64 * AST;
            __half* Vd = Vs + (cur ^ 1) * 64 * AST;
            #pragma unroll
            for (int i = 0; i < 2; i++) {
                int idx = tid + i * 256;
                int r = idx >> 3, u = idx & 7;
                CP16(smaddr(&Kd[r * AST + u * 8]), Kg + (size_t)(jn + r) * D_ + u * 8);
                CP16(smaddr(&Vd[r * AST + u * 8]), Vg + (size_t)(jn + r) * D_ + u * 8);
            }
            CP_COMMIT();
            CP_WAIT(1);
        } else {
            CP_WAIT(0);
        }
        __syncthreads();

        if (j0 <= rmax_w) {
            const __half* Kb = Ks + cur * 64 * AST;
            const __half* Vb = Vs + cur * 64 * AST;

            float sc[8][4];
            #pragma unroll
            for (int nf = 0; nf < 8; nf++)
                #pragma unroll
                for (int i = 0; i < 4; i++) sc[nf][i] = 0.f;

            #pragma unroll
            for (int kk = 0; kk < 4; kk++) {
                unsigned b[8][2];
                #pragma unroll
                for (int np = 0; np < 4; np++) {
                    unsigned addr = smaddr(&Kb[(np * 16 + brow) * AST + kk * 16 + bcol]);
                    LDM_X4(b[2 * np][0], b[2 * np][1], b[2 * np + 1][0], b[2 * np + 1][1], addr);
                }
                #pragma unroll
                for (int nf = 0; nf < 8; nf++)
                    mma16(sc[nf], qa[kk], b[nf][0], b[nf][1]);
            }

            bool need_mask = (j0 + 63 > row_w) || (j0 + 64 > len);
            if (need_mask) {
                #pragma unroll
                for (int nf = 0; nf < 8; nf++) {
                    int c0i = j0 + nf * 8 + 2 * t, c1i = c0i + 1;
                    if (c0i > r0 || c0i >= len) sc[nf][0] = -1e30f;
                    if (c1i > r0 || c1i >= len) sc[nf][1] = -1e30f;
                    if (c0i > r1 || c0i >= len) sc[nf][2] = -1e30f;
                    if (c1i > r1 || c1i >= len) sc[nf][3] = -1e30f;
                }
            }

            float rm0 = -1e30f, rm1 = -1e30f;
            #pragma unroll
            for (int nf = 0; nf < 8; nf++) {
                rm0 = fmaxf(rm0, fmaxf(sc[nf][0], sc[nf][1]));
                rm1 = fmaxf(rm1, fmaxf(sc[nf][2], sc[nf][3]));
            }
            rm0 = fmaxf(rm0, __shfl_xor_sync(0xffffffffu, rm0, 1));
            rm0 = fmaxf(rm0, __shfl_xor_sync(0xffffffffu, rm0, 2));
            rm1 = fmaxf(rm1, __shfl_xor_sync(0xffffffffu, rm1, 1));
            rm1 = fmaxf(rm1, __shfl_xor_sync(0xffffffffu, rm1, 2));

            float mn0 = fmaxf(m0, rm0), mn1 = fmaxf(m1, rm1);
            float al0 = __expf(m0 - mn0), al1 = __expf(m1 - mn1);
            m0 = mn0; m1 = mn1;

            float rs0 = 0.f, rs1 = 0.f;
            #pragma unroll
            for (int nf = 0; nf < 8; nf++) {
                sc[nf][0] = __expf(sc[nf][0] - mn0);
                sc[nf][1] = __expf(sc[nf][1] - mn0);
                sc[nf][2] = __expf(sc[nf][2] - mn1);
                sc[nf][3] = __expf(sc[nf][3] - mn1);
                rs0 += sc[nf][0] + sc[nf][1];
                rs1 += sc[nf][2] + sc[nf][3];
            }
            rs0 += __shfl_xor_sync(0xffffffffu, rs0, 1);
            rs0 += __shfl_xor_sync(0xffffffffu, rs0, 2);
            rs1 += __shfl_xor_sync(0xffffffffu, rs1, 1);
            rs1 += __shfl_xor_sync(0xffffffffu, rs1, 2);
            l0 = l0 * al0 + rs0;
            l1 = l1 * al1 + rs1;

            #pragma unroll
            for (int nf = 0; nf < 8; nf++) {
                oc[nf][0] *= al0; oc[nf][1] *= al0;
                oc[nf][2] *= al1; oc[nf][3] *= al1;
            }

            #pragma unroll
            for (int kk = 0; kk < 4; kk++) {
                unsigned pa[4];
                pa[0] = h2bits(sc[2 * kk][0],     sc[2 * kk][1]);
                pa[1] = h2bits(sc[2 * kk][2],     sc[2 * kk][3]);
                pa[2] = h2bits(sc[2 * kk + 1][0], sc[2 * kk + 1][1]);
                pa[3] = h2bits(sc[2 * kk + 1][2], sc[2 * kk + 1][3]);
                #pragma unroll
                for (int np = 0; np < 4; np++) {
                    unsigned v0, v1, v2, v3;
                    unsigned addr = smaddr(&Vb[(kk * 16 + vrow) * AST + np * 16 + vcol]);
                    LDM_X4T(v0, v1, v2, v3, addr);
                    mma16(oc[2 * np],     pa, v0, v1);
                    mma16(oc[2 * np + 1], pa, v2, v3);
                }
            }
        }
        __syncthreads();
    }

    // Epilogue: normalize, write O (half)
    float inv0 = 1.0f / l0, inv1 = 1.0f / l1;
    __half* Og = g_Oh + ((size_t)(n * L_ + row_w)) * D_ + h * DK_;
    #pragma unroll
    for (int nf = 0; nf < 8; nf++) {
        int cb = nf * 8 + 2 * t;
        *(unsigned*)(Og + (size_t)g * D_ + cb) =
            h2bits(oc[nf][0] * inv0, oc[nf][1] * inv0);
        *(unsigned*)(Og + (size_t)(g + 8) * D_ + cb) =
            h2bits(oc[nf][2] * inv1, oc[nf][3] * inv1);
    }
}

// ---------------------------------------------------------------------------
extern "C" void kernel_launch(void* const* d_in, const int* in_sizes, int n_in,
                              void* d_out, int out_size)
{
    const float* x_q = (const float*)d_in[0];
    const float* x_k = (const float*)d_in[1];
    const float* x_v = (const float*)d_in[2];
    const int*   pm  = (const int*)  d_in[3];
    // d_in[4] = attention_mask (causal) — handled analytically
    const float* Wq = (const float*)d_in[5];
    const float* bq = (const float*)d_in[6];
    const float* Wk = (const float*)d_in[7];
    const float* bk = (const float*)d_in[8];
    const float* Wv = (const float*)d_in[9];
    const float* bv = (const float*)d_in[10];
    const float* Wo = (const float*)d_in[11];
    const float* bo = (const float*)d_in[12];
    float* out = (float*)d_out;

    __half *xqh, *xkh, *xvh, *wqh, *wkh, *wvh, *woh, *Qh, *Kh, *Vh, *Oh;
    cudaGetSymbolAddress((void**)&xqh, g_xqh);
    cudaGetSymbolAddress((void**)&xkh, g_xkh);
    cudaGetSymbolAddress((void**)&xvh, g_xvh);
    cudaGetSymbolAddress((void**)&wqh, g_wqh);
    cudaGetSymbolAddress((void**)&wkh, g_wkh);
    cudaGetSymbolAddress((void**)&wvh, g_wvh);
    cudaGetSymbolAddress((void**)&woh, g_woh);
    cudaGetSymbolAddress((void**)&Qh,  g_Qh);
    cudaGetSymbolAddress((void**)&Kh,  g_Kh);
    cudaGetSymbolAddress((void**)&Vh,  g_Vh);
    cudaGetSymbolAddress((void**)&Oh,  g_Oh);

    cudaFuncSetAttribute(gemm_qkv, cudaFuncAttributeMaxDynamicSharedMemorySize,
                         GEMM_SMEM);
    cudaFuncSetAttribute(gemm_o, cudaFuncAttributeMaxDynamicSharedMemorySize,
                         GEMM_SMEM);
    cudaFuncSetAttribute(attn_h, cudaFuncAttributeMaxDynamicSharedMemorySize,
                         ATTN_SMEM);

    len_kernel<<<N_, 256>>>(pm);

    const int X4 = M_ * D_ / 4;   // 1,048,576
    const int W4 = D_ * D_ / 4;   // 65,536
    cvt3_kernel<<<dim3(X4 / 256, 3), 256>>>(
        (const float4*)x_q, (const float4*)x_k, (const float4*)x_v,
        (uint2*)xqh, (uint2*)xkh, (uint2*)xvh, X4);
    cvt4_kernel<<<dim3(W4 / 256, 4), 256>>>(
        (const float4*)Wq, (const float4*)Wk, (const float4*)Wv, (const float4*)Wo,
        (uint2*)wqh, (uint2*)wkh, (uint2*)wvh, (uint2*)woh, W4);

    gemm_qkv<<<dim3(M_ / 128, D_ / 128, 3), 256, GEMM_SMEM>>>(
        xqh, xkh, xvh, wqh, wkh, wvh, bq, bk, bv, Qh, Kh, Vh);

    attn_h<<<dim3(L_ / 128, H_, N_), 256, ATTN_SMEM>>>(0);

    gemm_o<<<dim3(M_ / 128, D_ / 128), 256, GEMM_SMEM>>>(Oh, woh, bo, out);
}

// round 9
// speedup vs baseline: 1.0086x; 1.0086x over previous
#include <cuda_runtime.h>
#include <cuda_fp16.h>
#include <math.h>

#define N_  4
#define L_  2048
#define D_  512
#define H_  8
#define DK_ 64
#define M_  (N_ * L_)

// Scratch (device globals: no allocation allowed in kernel_launch)
__device__ __half g_xqh[(size_t)M_ * D_];
__device__ __half g_xkh[(size_t)M_ * D_];
__device__ __half g_xvh[(size_t)M_ * D_];
__device__ __half g_wqh[(size_t)D_ * D_];
__device__ __half g_wkh[(size_t)D_ * D_];
__device__ __half g_wvh[(size_t)D_ * D_];
__device__ __half g_woh[(size_t)D_ * D_];
__device__ __half g_Qh[(size_t)M_ * D_];
__device__ __half g_Kh[(size_t)M_ * D_];
__device__ __half g_Vh[(size_t)M_ * D_];
__device__ __half g_Oh[(size_t)M_ * D_];
__device__ int    g_len[N_];

// ---------------------------------------------------------------------------
__device__ __forceinline__ void mma16(float c[4], const unsigned a[4],
                                      unsigned b0, unsigned b1) {
    asm volatile(
        "mma.sync.aligned.m16n8k16.row.col.f32.f16.f16.f32 "
        "{%0,%1,%2,%3}, {%4,%5,%6,%7}, {%8,%9}, {%0,%1,%2,%3};\n"
        : "+f"(c[0]), "+f"(c[1]), "+f"(c[2]), "+f"(c[3])
        : "r"(a[0]), "r"(a[1]), "r"(a[2]), "r"(a[3]), "r"(b0), "r"(b1));
}

__device__ __forceinline__ unsigned smaddr(const void* p) {
    return (unsigned)__cvta_generic_to_shared(p);
}
#define LDM_X4(r0, r1, r2, r3, addr) \
    asm volatile("ldmatrix.sync.aligned.m8n8.x4.shared.b16 {%0,%1,%2,%3}, [%4];" \
        : "=r"(r0), "=r"(r1), "=r"(r2), "=r"(r3) : "r"(addr))
#define LDM_X4T(r0, r1, r2, r3, addr) \
    asm volatile("ldmatrix.sync.aligned.m8n8.x4.trans.shared.b16 {%0,%1,%2,%3}, [%4];" \
        : "=r"(r0), "=r"(r1), "=r"(r2), "=r"(r3) : "r"(addr))
#define CP16(sm, gm) asm volatile("cp.async.cg.shared.global [%0], [%1], 16;\n" :: "r"(sm), "l"(gm))
#define CP_COMMIT()  asm volatile("cp.async.commit_group;\n")
#define CP_WAIT(n)   asm volatile("cp.async.wait_group %0;\n" :: "n"(n))

__device__ __forceinline__ unsigned h2bits(float lo, float hi) {
    __half2 h = __floats2half2_rn(lo, hi);
    return *(unsigned*)&h;
}

// ---------------------------------------------------------------------------
// Batched float -> half converters
// ---------------------------------------------------------------------------
__global__ void cvt3_kernel(const float4* __restrict__ s0,
                            const float4* __restrict__ s1,
                            const float4* __restrict__ s2,
                            uint2* __restrict__ d0, uint2* __restrict__ d1,
                            uint2* __restrict__ d2, int n4) {
    int i = blockIdx.x * 256 + threadIdx.x;
    if (i >= n4) return;
    const float4* s = (blockIdx.y == 0) ? s0 : (blockIdx.y == 1) ? s1 : s2;
    uint2*       d = (blockIdx.y == 0) ? d0 : (blockIdx.y == 1) ? d1 : d2;
    float4 v = s[i];
    d[i] = make_uint2(h2bits(v.x, v.y), h2bits(v.z, v.w));
}

__global__ void cvt4_kernel(const float4* __restrict__ s0,
                            const float4* __restrict__ s1,
                            const float4* __restrict__ s2,
                            const float4* __restrict__ s3,
                            uint2* __restrict__ d0, uint2* __restrict__ d1,
                            uint2* __restrict__ d2, uint2* __restrict__ d3,
                            int n4) {
    int i = blockIdx.x * 256 + threadIdx.x;
    if (i >= n4) return;
    const float4* s = (blockIdx.y == 0) ? s0 : (blockIdx.y == 1) ? s1
                    : (blockIdx.y == 2) ? s2 : s3;
    uint2*       d = (blockIdx.y == 0) ? d0 : (blockIdx.y == 1) ? d1
                    : (blockIdx.y == 2) ? d2 : d3;
    float4 v = s[i];
    d[i] = make_uint2(h2bits(v.x, v.y), h2bits(v.z, v.w));
}

// ---------------------------------------------------------------------------
// lengths: len[n] = 1 + max{ j : padding_mask[n][j] != 0 }
// ---------------------------------------------------------------------------
__global__ void len_kernel(const int* __restrict__ pm) {
    __shared__ int red[8];
    int n = blockIdx.x;
    int best = 0;
    for (int j = threadIdx.x; j < L_; j += 256)
        if (pm[(size_t)n * L_ + j] != 0) best = max(best, j + 1);
    #pragma unroll
    for (int off = 16; off; off >>= 1)
        best = max(best, __shfl_xor_sync(0xffffffffu, best, off));
    if ((threadIdx.x & 31) == 0) red[threadIdx.x >> 5] = best;
    __syncthreads();
    if (threadIdx.x == 0) {
        int b = red[0];
        #pragma unroll
        for (int w = 1; w < 8; w++) b = max(b, red[w]);
        g_len[n] = b;
    }
}

// ---------------------------------------------------------------------------
// GEMM body: C[128x128 tile] = (A @ W^T + bias) * scale, fp16 mma,
// cp.async 3-stage pipelined chunks (K=64), register-pipelined fragments.
// ---------------------------------------------------------------------------
#define GST 72
#define GNB (128 * GST)
#define GEMM_SMEM (3 * 2 * GNB * (int)sizeof(__half))

__device__ __forceinline__ void gemm_stage(__half* As, __half* Ws,
                                           const __half* __restrict__ A,
                                           const __half* __restrict__ W,
                                           int row0, int col0, int k0, int tid) {
    #pragma unroll
    for (int i = 0; i < 4; i++) {
        int idx = tid + i * 256;
        int r = idx >> 3, u = idx & 7;
        CP16(smaddr(&As[r * GST + u * 8]), A + (size_t)(row0 + r) * D_ + k0 + u * 8);
        CP16(smaddr(&Ws[r * GST + u * 8]), W + (size_t)(col0 + r) * D_ + k0 + u * 8);
    }
}

__device__ __forceinline__ void gemm_body(
    const __half* __restrict__ A, const __half* __restrict__ W,
    const float* __restrict__ bias, void* __restrict__ Cout, float scale,
    int half_out)
{
    extern __shared__ __half gsm[];
    __half* As = gsm;            // [3][GNB]
    __half* Ws = gsm + 3 * GNB;  // [3][GNB]

    int tid  = threadIdx.x;
    int lane = tid & 31, warp = tid >> 5;
    int g = lane >> 2, t = lane & 3;
    int wm = warp & 1, wn = warp >> 1;
    int row0 = blockIdx.x * 128;
    int col0 = blockIdx.y * 128;

    int arow = ((lane >> 3) & 1) * 8 + (lane & 7);
    int acol = (lane >> 4) * 8;
    int brow = (lane >> 4) * 8 + (lane & 7);
    int bcol = ((lane >> 3) & 1) * 8;

    float c[4][4][4];
    #pragma unroll
    for (int mf = 0; mf < 4; mf++)
        #pragma unroll
        for (int nf = 0; nf < 4; nf++)
            #pragma unroll
            for (int i = 0; i < 4; i++) c[mf][nf][i] = 0.f;

    // prologue: stage chunks 0 and 1
    gemm_stage(As,       Ws,       A, W, row0, col0, 0,  tid); CP_COMMIT();
    gemm_stage(As + GNB, Ws + GNB, A, W, row0, col0, 64, tid); CP_COMMIT();

    unsigned a[2][4][4], b[2][4][2];

    #pragma unroll 1
    for (int ch = 0; ch < 8; ch++) {
        int bi = ch % 3;
        if (ch < 7) { CP_WAIT(1); } else { CP_WAIT(0); }
        __syncthreads();
        // issue chunk ch+2 early (overlaps compute of ch and ch+1)
        if (ch + 2 < 8) {
            int nb = (ch + 2) % 3;
            gemm_stage(As + nb * GNB, Ws + nb * GNB, A, W, row0, col0,
                       (ch + 2) * 64, tid);
            CP_COMMIT();
        }

        const __half* Ab = As + bi * GNB;
        const __half* Wb = Ws + bi * GNB;

        // preload kk=0 fragments
        #pragma unroll
        for (int mf = 0; mf < 4; mf++) {
            unsigned addr = smaddr(&Ab[(wm * 64 + mf * 16 + arow) * GST + acol]);
            LDM_X4(a[0][mf][0], a[0][mf][1], a[0][mf][2], a[0][mf][3], addr);
        }
        #pragma unroll
        for (int np = 0; np < 2; np++) {
            unsigned addr = smaddr(&Wb[(wn * 32 + np * 16 + brow) * GST + bcol]);
            LDM_X4(b[0][2 * np][0], b[0][2 * np][1], b[0][2 * np + 1][0], b[0][2 * np + 1][1], addr);
        }

        #pragma unroll
        for (int kk = 0; kk < 4; kk++) {
            int fc = kk & 1;
            if (kk < 3) {
                int kn = (kk + 1) * 16;
                #pragma unroll
                for (int mf = 0; mf < 4; mf++) {
                    unsigned addr = smaddr(&Ab[(wm * 64 + mf * 16 + arow) * GST + kn + acol]);
                    LDM_X4(a[fc ^ 1][mf][0], a[fc ^ 1][mf][1], a[fc ^ 1][mf][2], a[fc ^ 1][mf][3], addr);
                }
                #pragma unroll
                for (int np = 0; np < 2; np++) {
                    unsigned addr = smaddr(&Wb[(wn * 32 + np * 16 + brow) * GST + kn + bcol]);
                    LDM_X4(b[fc ^ 1][2 * np][0], b[fc ^ 1][2 * np][1],
                           b[fc ^ 1][2 * np + 1][0], b[fc ^ 1][2 * np + 1][1], addr);
                }
            }
            #pragma unroll
            for (int mf = 0; mf < 4; mf++)
                #pragma unroll
                for (int nf = 0; nf < 4; nf++)
                    mma16(c[mf][nf], a[fc][mf], b[fc][nf][0], b[fc][nf][1]);
        }
    }

    // Epilogue
    #pragma unroll
    for (int mf = 0; mf < 4; mf++) {
        int r0 = row0 + wm * 64 + mf * 16 + g;
        #pragma unroll
        for (int nf = 0; nf < 4; nf++) {
            int cc = col0 + wn * 32 + nf * 8 + 2 * t;
            float b0 = bias[cc], b1 = bias[cc + 1];
            float v00 = (c[mf][nf][0] + b0) * scale;
            float v01 = (c[mf][nf][1] + b1) * scale;
            float v10 = (c[mf][nf][2] + b0) * scale;
            float v11 = (c[mf][nf][3] + b1) * scale;
            if (half_out) {
                __half* C = (__half*)Cout;
                *(unsigned*)(C + (size_t)r0 * D_ + cc)       = h2bits(v00, v01);
                *(unsigned*)(C + (size_t)(r0 + 8) * D_ + cc) = h2bits(v10, v11);
            } else {
                float* C = (float*)Cout;
                *(float2*)(C + (size_t)r0 * D_ + cc)       = make_float2(v00, v01);
                *(float2*)(C + (size_t)(r0 + 8) * D_ + cc) = make_float2(v10, v11);
            }
        }
    }
}

// Fused Q/K/V projection: blockIdx.z selects the operand set.
// Q scale folds in 1/sqrt(dk) AND log2(e) so attention can use exp2f.
__global__ __launch_bounds__(256, 2) void gemm_qkv(
    const __half* __restrict__ xq, const __half* __restrict__ xk,
    const __half* __restrict__ xv,
    const __half* __restrict__ wq, const __half* __restrict__ wk,
    const __half* __restrict__ wv,
    const float* __restrict__ bq, const float* __restrict__ bk,
    const float* __restrict__ bv,
    __half* __restrict__ Q, __half* __restrict__ K, __half* __restrict__ V)
{
    int z = blockIdx.z;
    const __half* A = (z == 0) ? xq : (z == 1) ? xk : xv;
    const __half* W = (z == 0) ? wq : (z == 1) ? wk : wv;
    const float* bias = (z == 0) ? bq : (z == 1) ? bk : bv;
    __half* C = (z == 0) ? Q : (z == 1) ? K : V;
    float scale = (z == 0) ? (0.125f * 1.4426950408889634f) : 1.0f;
    gemm_body(A, W, bias, C, scale, 1);
}

// Output projection (float out)
__global__ __launch_bounds__(256, 2) void gemm_o(
    const __half* __restrict__ A, const __half* __restrict__ W,
    const float* __restrict__ bias, float* __restrict__ C)
{
    gemm_body(A, W, bias, C, 1.0f, 0);
}

// ---------------------------------------------------------------------------
// Flash attention, fp16 mma. Block = (128 q-rows, head, batch), 8 warps.
// Scores are in log2 domain (Q pre-scaled by log2(e)/sqrt(dk)) -> exp2f.
// Heavy (high-q0) blocks launch first for causal load balance.
// ---------------------------------------------------------------------------
#define AST 72
#define ATTN_SMEM (4 * 64 * AST * (int)sizeof(__half))

__global__ __launch_bounds__(256, 2) void attn_h(int dummy) {
    extern __shared__ __half asm_[];
    __half* Ks = asm_;                        // [2][64*AST]
    __half* Vs = asm_ + 2 * 64 * AST;         // [2][64*AST]

    int tid  = threadIdx.x;
    int lane = tid & 31, warp = tid >> 5;
    int g = lane >> 2, t = lane & 3;
    int q0 = ((int)gridDim.x - 1 - (int)blockIdx.x) * 128;
    int h  = blockIdx.y;
    int n  = blockIdx.z;

    int row_w = q0 + warp * 16;

    const __half* Qg = g_Qh + (size_t)n * L_ * D_ + (size_t)row_w * D_ + h * DK_;
    const __half* Kg = g_Kh + (size_t)n * L_ * D_ + h * DK_;
    const __half* Vg = g_Vh + (size_t)n * L_ * D_ + h * DK_;

    int brow = (lane >> 4) * 8 + (lane & 7);
    int bcol = ((lane >> 3) & 1) * 8;
    int vrow = ((lane >> 3) & 1) * 8 + (lane & 7);
    int vcol = (lane >> 4) * 8;

    unsigned qa[4][4];
    #pragma unroll
    for (int kk = 0; kk < 4; kk++) {
        qa[kk][0] = *(const unsigned*)&Qg[(size_t)g * D_       + kk * 16 + 2 * t];
        qa[kk][1] = *(const unsigned*)&Qg[(size_t)(g + 8) * D_ + kk * 16 + 2 * t];
        qa[kk][2] = *(const unsigned*)&Qg[(size_t)g * D_       + kk * 16 + 2 * t + 8];
        qa[kk][3] = *(const unsigned*)&Qg[(size_t)(g + 8) * D_ + kk * 16 + 2 * t + 8];
    }

    float oc[8][4];
    #pragma unroll
    for (int nf = 0; nf < 8; nf++)
        #pragma unroll
        for (int i = 0; i < 4; i++) oc[nf][i] = 0.f;

    float m0 = -1e30f, m1 = -1e30f, l0 = 0.f, l1 = 0.f;
    int r0 = row_w + g;
    int r1 = r0 + 8;
    int rmax_w = row_w + 15;

    int len   = g_len[n];
    int jend  = min(q0 + 128, len);
    int tiles = (jend + 63) >> 6;

    {
        #pragma unroll
        for (int i = 0; i < 2; i++) {
            int idx = tid + i * 256;
            int r = idx >> 3, u = idx & 7;
            CP16(smaddr(&Ks[r * AST + u * 8]), Kg + (size_t)r * D_ + u * 8);
            CP16(smaddr(&Vs[r * AST + u * 8]), Vg + (size_t)r * D_ + u * 8);
        }
        CP_COMMIT();
    }

    #pragma unroll 1
    for (int it = 0; it < tiles; it++) {
        int cur = it & 1;
        int j0  = it * 64;
        if (it + 1 < tiles) {
            int jn = j0 + 64;
            __half* Kd = Ks + (cur ^ 1) * 64 * AST;
            __half* Vd = Vs + (cur ^ 1) * 64 * AST;
            #pragma unroll
            for (int i = 0; i < 2; i++) {
                int idx = tid + i * 256;
                int r = idx >> 3, u = idx & 7;
                CP16(smaddr(&Kd[r * AST + u * 8]), Kg + (size_t)(jn + r) * D_ + u * 8);
                CP16(smaddr(&Vd[r * AST + u * 8]), Vg + (size_t)(jn + r) * D_ + u * 8);
            }
            CP_COMMIT();
            CP_WAIT(1);
        } else {
            CP_WAIT(0);
        }
        __syncthreads();

        if (j0 <= rmax_w) {
            const __half* Kb = Ks + cur * 64 * AST;
            const __half* Vb = Vs + cur * 64 * AST;

            float sc[8][4];
            #pragma unroll
            for (int nf = 0; nf < 8; nf++)
                #pragma unroll
                for (int i = 0; i < 4; i++) sc[nf][i] = 0.f;

            #pragma unroll
            for (int kk = 0; kk < 4; kk++) {
                unsigned b[8][2];
                #pragma unroll
                for (int np = 0; np < 4; np++) {
                    unsigned addr = smaddr(&Kb[(np * 16 + brow) * AST + kk * 16 + bcol]);
                    LDM_X4(b[2 * np][0], b[2 * np][1], b[2 * np + 1][0], b[2 * np + 1][1], addr);
                }
                #pragma unroll
                for (int nf = 0; nf < 8; nf++)
                    mma16(sc[nf], qa[kk], b[nf][0], b[nf][1]);
            }

            bool need_mask = (j0 + 63 > row_w) || (j0 + 64 > len);
            if (need_mask) {
                #pragma unroll
                for (int nf = 0; nf < 8; nf++) {
                    int c0i = j0 + nf * 8 + 2 * t, c1i = c0i + 1;
                    if (c0i > r0 || c0i >= len) sc[nf][0] = -1e30f;
                    if (c1i > r0 || c1i >= len) sc[nf][1] = -1e30f;
                    if (c0i > r1 || c0i >= len) sc[nf][2] = -1e30f;
                    if (c1i > r1 || c1i >= len) sc[nf][3] = -1e30f;
                }
            }

            float rm0 = -1e30f, rm1 = -1e30f;
            #pragma unroll
            for (int nf = 0; nf < 8; nf++) {
                rm0 = fmaxf(rm0, fmaxf(sc[nf][0], sc[nf][1]));
                rm1 = fmaxf(rm1, fmaxf(sc[nf][2], sc[nf][3]));
            }
            rm0 = fmaxf(rm0, __shfl_xor_sync(0xffffffffu, rm0, 1));
            rm0 = fmaxf(rm0, __shfl_xor_sync(0xffffffffu, rm0, 2));
            rm1 = fmaxf(rm1, __shfl_xor_sync(0xffffffffu, rm1, 1));
            rm1 = fmaxf(rm1, __shfl_xor_sync(0xffffffffu, rm1, 2));

            float mn0 = fmaxf(m0, rm0), mn1 = fmaxf(m1, rm1);
            float al0 = exp2f(m0 - mn0), al1 = exp2f(m1 - mn1);
            m0 = mn0; m1 = mn1;

            float rs0 = 0.f, rs1 = 0.f;
            #pragma unroll
            for (int nf = 0; nf < 8; nf++) {
                sc[nf][0] = exp2f(sc[nf][0] - mn0);
                sc[nf][1] = exp2f(sc[nf][1] - mn0);
                sc[nf][2] = exp2f(sc[nf][2] - mn1);
                sc[nf][3] = exp2f(sc[nf][3] - mn1);
                rs0 += sc[nf][0] + sc[nf][1];
                rs1 += sc[nf][2] + sc[nf][3];
            }
            rs0 += __shfl_xor_sync(0xffffffffu, rs0, 1);
            rs0 += __shfl_xor_sync(0xffffffffu, rs0, 2);
            rs1 += __shfl_xor_sync(0xffffffffu, rs1, 1);
            rs1 += __shfl_xor_sync(0xffffffffu, rs1, 2);
            l0 = l0 * al0 + rs0;
            l1 = l1 * al1 + rs1;

            #pragma unroll
            for (int nf = 0; nf < 8; nf++) {
                oc[nf][0] *= al0; oc[nf][1] *= al0;
                oc[nf][2] *= al1; oc[nf][3] *= al1;
            }

            #pragma unroll
            for (int kk = 0; kk < 4; kk++) {
                unsigned pa[4];
                pa[0] = h2bits(sc[2 * kk][0],     sc[2 * kk][1]);
                pa[1] = h2bits(sc[2 * kk][2],     sc[2 * kk][3]);
                pa[2] = h2bits(sc[2 * kk + 1][0], sc[2 * kk + 1][1]);
                pa[3] = h2bits(sc[2 * kk + 1][2], sc[2 * kk + 1][3]);
                #pragma unroll
                for (int np = 0; np < 4; np++) {
                    unsigned v0, v1, v2, v3;
                    unsigned addr = smaddr(&Vb[(kk * 16 + vrow) * AST + np * 16 + vcol]);
                    LDM_X4T(v0, v1, v2, v3, addr);
                    mma16(oc[2 * np],     pa, v0, v1);
                    mma16(oc[2 * np + 1], pa, v2, v3);
                }
            }
        }
        __syncthreads();
    }

    float inv0 = 1.0f / l0, inv1 = 1.0f / l1;
    __half* Og = g_Oh + ((size_t)(n * L_ + row_w)) * D_ + h * DK_;
    #pragma unroll
    for (int nf = 0; nf < 8; nf++) {
        int cb = nf * 8 + 2 * t;
        *(unsigned*)(Og + (size_t)g * D_ + cb) =
            h2bits(oc[nf][0] * inv0, oc[nf][1] * inv0);
        *(unsigned*)(Og + (size_t)(g + 8) * D_ + cb) =
            h2bits(oc[nf][2] * inv1, oc[nf][3] * inv1);
    }
}

// ---------------------------------------------------------------------------
extern "C" void kernel_launch(void* const* d_in, const int* in_sizes, int n_in,
                              void* d_out, int out_size)
{
    const float* x_q = (const float*)d_in[0];
    const float* x_k = (const float*)d_in[1];
    const float* x_v = (const float*)d_in[2];
    const int*   pm  = (const int*)  d_in[3];
    // d_in[4] = attention_mask (causal) — handled analytically
    const float* Wq = (const float*)d_in[5];
    const float* bq = (const float*)d_in[6];
    const float* Wk = (const float*)d_in[7];
    const float* bk = (const float*)d_in[8];
    const float* Wv = (const float*)d_in[9];
    const float* bv = (const float*)d_in[10];
    const float* Wo = (const float*)d_in[11];
    const float* bo = (const float*)d_in[12];
    float* out = (float*)d_out;

    __half *xqh, *xkh, *xvh, *wqh, *wkh, *wvh, *woh, *Qh, *Kh, *Vh, *Oh;
    cudaGetSymbolAddress((void**)&xqh, g_xqh);
    cudaGetSymbolAddress((void**)&xkh, g_xkh);
    cudaGetSymbolAddress((void**)&xvh, g_xvh);
    cudaGetSymbolAddress((void**)&wqh, g_wqh);
    cudaGetSymbolAddress((void**)&wkh, g_wkh);
    cudaGetSymbolAddress((void**)&wvh, g_wvh);
    cudaGetSymbolAddress((void**)&woh, g_woh);
    cudaGetSymbolAddress((void**)&Qh,  g_Qh);
    cudaGetSymbolAddress((void**)&Kh,  g_Kh);
    cudaGetSymbolAddress((void**)&Vh,  g_Vh);
    cudaGetSymbolAddress((void**)&Oh,  g_Oh);

    cudaFuncSetAttribute(gemm_qkv, cudaFuncAttributeMaxDynamicSharedMemorySize,
                         GEMM_SMEM);
    cudaFuncSetAttribute(gemm_o, cudaFuncAttributeMaxDynamicSharedMemorySize,
                         GEMM_SMEM);
    cudaFuncSetAttribute(attn_h, cudaFuncAttributeMaxDynamicSharedMemorySize,
                         ATTN_SMEM);

    len_kernel<<<N_, 256>>>(pm);

    const int X4 = M_ * D_ / 4;   // 1,048,576
    const int W4 = D_ * D_ / 4;   // 65,536
    cvt3_kernel<<<dim3(X4 / 256, 3), 256>>>(
        (const float4*)x_q, (const float4*)x_k, (const float4*)x_v,
        (uint2*)xqh, (uint2*)xkh, (uint2*)xvh, X4);
    cvt4_kernel<<<dim3(W4 / 256, 4), 256>>>(
        (const float4*)Wq, (const float4*)Wk, (const float4*)Wv, (const float4*)Wo,
        (uint2*)wqh, (uint2*)wkh, (uint2*)wvh, (uint2*)woh, W4);

    gemm_qkv<<<dim3(M_ / 128, D_ / 128, 3), 256, GEMM_SMEM>>>(
        xqh, xkh, xvh, wqh, wkh, wvh, bq, bk, bv, Qh, Kh, Vh);

    attn_h<<<dim3(L_ / 128, H_, N_), 256, ATTN_SMEM>>>(0);

    gemm_o<<<dim3(M_ / 128, D_ / 128), 256, GEMM_SMEM>>>(Oh, woh, bo, out);
}

// round 10
// speedup vs baseline: 1.0712x; 1.0621x over previous
#include <cuda_runtime.h>
#include <cuda_fp16.h>
#include <math.h>

#define N_  4
#define L_  2048
#define D_  512
#define H_  8
#define DK_ 64
#define M_  (N_ * L_)

// Scratch (device globals: no allocation allowed in kernel_launch)
__device__ __half g_xqh[(size_t)M_ * D_];
__device__ __half g_xkh[(size_t)M_ * D_];
__device__ __half g_xvh[(size_t)M_ * D_];
__device__ __half g_wqh[(size_t)D_ * D_];
__device__ __half g_wkh[(size_t)D_ * D_];
__device__ __half g_wvh[(size_t)D_ * D_];
__device__ __half g_woh[(size_t)D_ * D_];
__device__ __half g_Qh[(size_t)M_ * D_];
__device__ __half g_Kh[(size_t)M_ * D_];
__device__ __half g_Vh[(size_t)M_ * D_];
__device__ __half g_Oh[(size_t)M_ * D_];
__device__ int    g_len[N_];

#define HONES 0x3C003C00u   // half2(1.0, 1.0)

// ---------------------------------------------------------------------------
__device__ __forceinline__ void mma16(float c[4], const unsigned a[4],
                                      unsigned b0, unsigned b1) {
    asm volatile(
        "mma.sync.aligned.m16n8k16.row.col.f32.f16.f16.f32 "
        "{%0,%1,%2,%3}, {%4,%5,%6,%7}, {%8,%9}, {%0,%1,%2,%3};\n"
        : "+f"(c[0]), "+f"(c[1]), "+f"(c[2]), "+f"(c[3])
        : "r"(a[0]), "r"(a[1]), "r"(a[2]), "r"(a[3]), "r"(b0), "r"(b1));
}

__device__ __forceinline__ unsigned smaddr(const void* p) {
    return (unsigned)__cvta_generic_to_shared(p);
}
#define LDM_X4(r0, r1, r2, r3, addr) \
    asm volatile("ldmatrix.sync.aligned.m8n8.x4.shared.b16 {%0,%1,%2,%3}, [%4];" \
        : "=r"(r0), "=r"(r1), "=r"(r2), "=r"(r3) : "r"(addr))
#define LDM_X4T(r0, r1, r2, r3, addr) \
    asm volatile("ldmatrix.sync.aligned.m8n8.x4.trans.shared.b16 {%0,%1,%2,%3}, [%4];" \
        : "=r"(r0), "=r"(r1), "=r"(r2), "=r"(r3) : "r"(addr))
#define CP16(sm, gm) asm volatile("cp.async.cg.shared.global [%0], [%1], 16;\n" :: "r"(sm), "l"(gm))
#define CP_COMMIT()  asm volatile("cp.async.commit_group;\n")
#define CP_WAIT(n)   asm volatile("cp.async.wait_group %0;\n" :: "n"(n))

__device__ __forceinline__ unsigned h2bits(float lo, float hi) {
    __half2 h = __floats2half2_rn(lo, hi);
    return *(unsigned*)&h;
}

// packed half2 2^x
__device__ __forceinline__ unsigned ex2h2(unsigned x) {
    unsigned r;
    asm volatile("ex2.approx.f16x2 %0, %1;" : "=r"(r) : "r"(x));
    return r;
}

// ---------------------------------------------------------------------------
// Batched float -> half converters (2 float4 per thread for MLP)
// ---------------------------------------------------------------------------
__global__ void cvt3_kernel(const float4* __restrict__ s0,
                            const float4* __restrict__ s1,
                            const float4* __restrict__ s2,
                            uint2* __restrict__ d0, uint2* __restrict__ d1,
                            uint2* __restrict__ d2, int n4) {
    int i = blockIdx.x * 512 + threadIdx.x;
    const float4* s = (blockIdx.y == 0) ? s0 : (blockIdx.y == 1) ? s1 : s2;
    uint2*       d = (blockIdx.y == 0) ? d0 : (blockIdx.y == 1) ? d1 : d2;
    if (i + 256 < n4) {
        float4 v0 = s[i], v1 = s[i + 256];
        d[i]       = make_uint2(h2bits(v0.x, v0.y), h2bits(v0.z, v0.w));
        d[i + 256] = make_uint2(h2bits(v1.x, v1.y), h2bits(v1.z, v1.w));
    } else if (i < n4) {
        float4 v0 = s[i];
        d[i] = make_uint2(h2bits(v0.x, v0.y), h2bits(v0.z, v0.w));
    }
}

__global__ void cvt4_kernel(const float4* __restrict__ s0,
                            const float4* __restrict__ s1,
                            const float4* __restrict__ s2,
                            const float4* __restrict__ s3,
                            uint2* __restrict__ d0, uint2* __restrict__ d1,
                            uint2* __restrict__ d2, uint2* __restrict__ d3,
                            int n4) {
    int i = blockIdx.x * 512 + threadIdx.x;
    const float4* s = (blockIdx.y == 0) ? s0 : (blockIdx.y == 1) ? s1
                    : (blockIdx.y == 2) ? s2 : s3;
    uint2*       d = (blockIdx.y == 0) ? d0 : (blockIdx.y == 1) ? d1
                    : (blockIdx.y == 2) ? d2 : d3;
    if (i + 256 < n4) {
        float4 v0 = s[i], v1 = s[i + 256];
        d[i]       = make_uint2(h2bits(v0.x, v0.y), h2bits(v0.z, v0.w));
        d[i + 256] = make_uint2(h2bits(v1.x, v1.y), h2bits(v1.z, v1.w));
    } else if (i < n4) {
        float4 v0 = s[i];
        d[i] = make_uint2(h2bits(v0.x, v0.y), h2bits(v0.z, v0.w));
    }
}

// ---------------------------------------------------------------------------
// lengths: len[n] = 1 + max{ j : padding_mask[n][j] != 0 }
// ---------------------------------------------------------------------------
__global__ void len_kernel(const int* __restrict__ pm) {
    __shared__ int red[8];
    int n = blockIdx.x;
    int best = 0;
    for (int j = threadIdx.x; j < L_; j += 256)
        if (pm[(size_t)n * L_ + j] != 0) best = max(best, j + 1);
    #pragma unroll
    for (int off = 16; off; off >>= 1)
        best = max(best, __shfl_xor_sync(0xffffffffu, best, off));
    if ((threadIdx.x & 31) == 0) red[threadIdx.x >> 5] = best;
    __syncthreads();
    if (threadIdx.x == 0) {
        int b = red[0];
        #pragma unroll
        for (int w = 1; w < 8; w++) b = max(b, red[w]);
        g_len[n] = b;
    }
}

// ---------------------------------------------------------------------------
// GEMM body (unchanged from R9): 128x128 tile, fp16 mma, cp.async 3-stage.
// ---------------------------------------------------------------------------
#define GST 72
#define GNB (128 * GST)
#define GEMM_SMEM (3 * 2 * GNB * (int)sizeof(__half))

__device__ __forceinline__ void gemm_stage(__half* As, __half* Ws,
                                           const __half* __restrict__ A,
                                           const __half* __restrict__ W,
                                           int row0, int col0, int k0, int tid) {
    #pragma unroll
    for (int i = 0; i < 4; i++) {
        int idx = tid + i * 256;
        int r = idx >> 3, u = idx & 7;
        CP16(smaddr(&As[r * GST + u * 8]), A + (size_t)(row0 + r) * D_ + k0 + u * 8);
        CP16(smaddr(&Ws[r * GST + u * 8]), W + (size_t)(col0 + r) * D_ + k0 + u * 8);
    }
}

__device__ __forceinline__ void gemm_body(
    const __half* __restrict__ A, const __half* __restrict__ W,
    const float* __restrict__ bias, void* __restrict__ Cout, float scale,
    int half_out)
{
    extern __shared__ __half gsm[];
    __half* As = gsm;            // [3][GNB]
    __half* Ws = gsm + 3 * GNB;  // [3][GNB]

    int tid  = threadIdx.x;
    int lane = tid & 31, warp = tid >> 5;
    int g = lane >> 2, t = lane & 3;
    int wm = warp & 1, wn = warp >> 1;
    int row0 = blockIdx.x * 128;
    int col0 = blockIdx.y * 128;

    int arow = ((lane >> 3) & 1) * 8 + (lane & 7);
    int acol = (lane >> 4) * 8;
    int brow = (lane >> 4) * 8 + (lane & 7);
    int bcol = ((lane >> 3) & 1) * 8;

    float c[4][4][4];
    #pragma unroll
    for (int mf = 0; mf < 4; mf++)
        #pragma unroll
        for (int nf = 0; nf < 4; nf++)
            #pragma unroll
            for (int i = 0; i < 4; i++) c[mf][nf][i] = 0.f;

    gemm_stage(As,       Ws,       A, W, row0, col0, 0,  tid); CP_COMMIT();
    gemm_stage(As + GNB, Ws + GNB, A, W, row0, col0, 64, tid); CP_COMMIT();

    unsigned a[2][4][4], b[2][4][2];

    #pragma unroll 1
    for (int ch = 0; ch < 8; ch++) {
        int bi = ch % 3;
        if (ch < 7) { CP_WAIT(1); } else { CP_WAIT(0); }
        __syncthreads();
        if (ch + 2 < 8) {
            int nb = (ch + 2) % 3;
            gemm_stage(As + nb * GNB, Ws + nb * GNB, A, W, row0, col0,
                       (ch + 2) * 64, tid);
            CP_COMMIT();
        }

        const __half* Ab = As + bi * GNB;
        const __half* Wb = Ws + bi * GNB;

        #pragma unroll
        for (int mf = 0; mf < 4; mf++) {
            unsigned addr = smaddr(&Ab[(wm * 64 + mf * 16 + arow) * GST + acol]);
            LDM_X4(a[0][mf][0], a[0][mf][1], a[0][mf][2], a[0][mf][3], addr);
        }
        #pragma unroll
        for (int np = 0; np < 2; np++) {
            unsigned addr = smaddr(&Wb[(wn * 32 + np * 16 + brow) * GST + bcol]);
            LDM_X4(b[0][2 * np][0], b[0][2 * np][1], b[0][2 * np + 1][0], b[0][2 * np + 1][1], addr);
        }

        #pragma unroll
        for (int kk = 0; kk < 4; kk++) {
            int fc = kk & 1;
            if (kk < 3) {
                int kn = (kk + 1) * 16;
                #pragma unroll
                for (int mf = 0; mf < 4; mf++) {
                    unsigned addr = smaddr(&Ab[(wm * 64 + mf * 16 + arow) * GST + kn + acol]);
                    LDM_X4(a[fc ^ 1][mf][0], a[fc ^ 1][mf][1], a[fc ^ 1][mf][2], a[fc ^ 1][mf][3], addr);
                }
                #pragma unroll
                for (int np = 0; np < 2; np++) {
                    unsigned addr = smaddr(&Wb[(wn * 32 + np * 16 + brow) * GST + kn + bcol]);
                    LDM_X4(b[fc ^ 1][2 * np][0], b[fc ^ 1][2 * np][1],
                           b[fc ^ 1][2 * np + 1][0], b[fc ^ 1][2 * np + 1][1], addr);
                }
            }
            #pragma unroll
            for (int mf = 0; mf < 4; mf++)
                #pragma unroll
                for (int nf = 0; nf < 4; nf++)
                    mma16(c[mf][nf], a[fc][mf], b[fc][nf][0], b[fc][nf][1]);
        }
    }

    // Epilogue
    #pragma unroll
    for (int mf = 0; mf < 4; mf++) {
        int r0 = row0 + wm * 64 + mf * 16 + g;
        #pragma unroll
        for (int nf = 0; nf < 4; nf++) {
            int cc = col0 + wn * 32 + nf * 8 + 2 * t;
            float b0 = bias[cc], b1 = bias[cc + 1];
            float v00 = (c[mf][nf][0] + b0) * scale;
            float v01 = (c[mf][nf][1] + b1) * scale;
            float v10 = (c[mf][nf][2] + b0) * scale;
            float v11 = (c[mf][nf][3] + b1) * scale;
            if (half_out) {
                __half* C = (__half*)Cout;
                *(unsigned*)(C + (size_t)r0 * D_ + cc)       = h2bits(v00, v01);
                *(unsigned*)(C + (size_t)(r0 + 8) * D_ + cc) = h2bits(v10, v11);
            } else {
                float* C = (float*)Cout;
                *(float2*)(C + (size_t)r0 * D_ + cc)       = make_float2(v00, v01);
                *(float2*)(C + (size_t)(r0 + 8) * D_ + cc) = make_float2(v10, v11);
            }
        }
    }
}

// Fused Q/K/V projection. Q scale folds 1/sqrt(dk) and log2(e) -> exp2 domain.
__global__ __launch_bounds__(256, 2) void gemm_qkv(
    const __half* __restrict__ xq, const __half* __restrict__ xk,
    const __half* __restrict__ xv,
    const __half* __restrict__ wq, const __half* __restrict__ wk,
    const __half* __restrict__ wv,
    const float* __restrict__ bq, const float* __restrict__ bk,
    const float* __restrict__ bv,
    __half* __restrict__ Q, __half* __restrict__ K, __half* __restrict__ V)
{
    int z = blockIdx.z;
    const __half* A = (z == 0) ? xq : (z == 1) ? xk : xv;
    const __half* W = (z == 0) ? wq : (z == 1) ? wk : wv;
    const float* bias = (z == 0) ? bq : (z == 1) ? bk : bv;
    __half* C = (z == 0) ? Q : (z == 1) ? K : V;
    float scale = (z == 0) ? (0.125f * 1.4426950408889634f) : 1.0f;
    gemm_body(A, W, bias, C, scale, 1);
}

__global__ __launch_bounds__(256, 2) void gemm_o(
    const __half* __restrict__ A, const __half* __restrict__ W,
    const float* __restrict__ bias, float* __restrict__ C)
{
    gemm_body(A, W, bias, C, 1.0f, 0);
}

// ---------------------------------------------------------------------------
// Flash attention, fp16 mma. Block = (128 q-rows, head, batch), 8 warps.
// log2-domain scores; exp via ex2.approx.f16x2 (half the MUFU ops);
// row-sum l accumulated by an extra MMA against a constant all-ones B
// fragment (no FADD/SHFL chain, auto-rescaled by alpha).
// ---------------------------------------------------------------------------
#define AST 72
#define ATTN_SMEM (4 * 64 * AST * (int)sizeof(__half))

__global__ __launch_bounds__(256, 2) void attn_h(int dummy) {
    extern __shared__ __half asm_[];
    __half* Ks = asm_;                        // [2][64*AST]
    __half* Vs = asm_ + 2 * 64 * AST;         // [2][64*AST]

    int tid  = threadIdx.x;
    int lane = tid & 31, warp = tid >> 5;
    int g = lane >> 2, t = lane & 3;
    int q0 = ((int)gridDim.x - 1 - (int)blockIdx.x) * 128;
    int h  = blockIdx.y;
    int n  = blockIdx.z;

    int row_w = q0 + warp * 16;

    const __half* Qg = g_Qh + (size_t)n * L_ * D_ + (size_t)row_w * D_ + h * DK_;
    const __half* Kg = g_Kh + (size_t)n * L_ * D_ + h * DK_;
    const __half* Vg = g_Vh + (size_t)n * L_ * D_ + h * DK_;

    int brow = (lane >> 4) * 8 + (lane & 7);
    int bcol = ((lane >> 3) & 1) * 8;
    int vrow = ((lane >> 3) & 1) * 8 + (lane & 7);
    int vcol = (lane >> 4) * 8;

    unsigned qa[4][4];
    #pragma unroll
    for (int kk = 0; kk < 4; kk++) {
        qa[kk][0] = *(const unsigned*)&Qg[(size_t)g * D_       + kk * 16 + 2 * t];
        qa[kk][1] = *(const unsigned*)&Qg[(size_t)(g + 8) * D_ + kk * 16 + 2 * t];
        qa[kk][2] = *(const unsigned*)&Qg[(size_t)g * D_       + kk * 16 + 2 * t + 8];
        qa[kk][3] = *(const unsigned*)&Qg[(size_t)(g + 8) * D_ + kk * 16 + 2 * t + 8];
    }

    float oc[8][4];
    #pragma unroll
    for (int nf = 0; nf < 8; nf++)
        #pragma unroll
        for (int i = 0; i < 4; i++) oc[nf][i] = 0.f;
    float ol[4] = {0.f, 0.f, 0.f, 0.f};   // row-sum accumulator (ones column)

    float m0 = -1e30f, m1 = -1e30f;
    int r0 = row_w + g;
    int r1 = r0 + 8;
    int rmax_w = row_w + 15;

    int len   = g_len[n];
    int jend  = min(q0 + 128, len);
    int tiles = (jend + 63) >> 6;

    {
        #pragma unroll
        for (int i = 0; i < 2; i++) {
            int idx = tid + i * 256;
            int r = idx >> 3, u = idx & 7;
            CP16(smaddr(&Ks[r * AST + u * 8]), Kg + (size_t)r * D_ + u * 8);
            CP16(smaddr(&Vs[r * AST + u * 8]), Vg + (size_t)r * D_ + u * 8);
        }
        CP_COMMIT();
    }

    #pragma unroll 1
    for (int it = 0; it < tiles; it++) {
        int cur = it & 1;
        int j0  = it * 64;
        if (it + 1 < tiles) {
            int jn = j0 + 64;
            __half* Kd = Ks + (cur ^ 1) * 64 * AST;
            __half* Vd = Vs + (cur ^ 1) * 64 * AST;
            #pragma unroll
            for (int i = 0; i < 2; i++) {
                int idx = tid + i * 256;
                int r = idx >> 3, u = idx & 7;
                CP16(smaddr(&Kd[r * AST + u * 8]), Kg + (size_t)(jn + r) * D_ + u * 8);
                CP16(smaddr(&Vd[r * AST + u * 8]), Vg + (size_t)(jn + r) * D_ + u * 8);
            }
            CP_COMMIT();
            CP_WAIT(1);
        } else {
            CP_WAIT(0);
        }
        __syncthreads();

        if (j0 <= rmax_w) {
            const __half* Kb = Ks + cur * 64 * AST;
            const __half* Vb = Vs + cur * 64 * AST;

            // S = Q K^T (log2 domain)
            float sc[8][4];
            #pragma unroll
            for (int nf = 0; nf < 8; nf++)
                #pragma unroll
                for (int i = 0; i < 4; i++) sc[nf][i] = 0.f;

            #pragma unroll
            for (int kk = 0; kk < 4; kk++) {
                unsigned b[8][2];
                #pragma unroll
                for (int np = 0; np < 4; np++) {
                    unsigned addr = smaddr(&Kb[(np * 16 + brow) * AST + kk * 16 + bcol]);
                    LDM_X4(b[2 * np][0], b[2 * np][1], b[2 * np + 1][0], b[2 * np + 1][1], addr);
                }
                #pragma unroll
                for (int nf = 0; nf < 8; nf++)
                    mma16(sc[nf], qa[kk], b[nf][0], b[nf][1]);
            }

            // Masking only on diagonal / len-boundary tiles
            bool need_mask = (j0 + 63 > row_w) || (j0 + 64 > len);
            if (need_mask) {
                #pragma unroll
                for (int nf = 0; nf < 8; nf++) {
                    int c0i = j0 + nf * 8 + 2 * t, c1i = c0i + 1;
                    if (c0i > r0 || c0i >= len) sc[nf][0] = -1e30f;
                    if (c1i > r0 || c1i >= len) sc[nf][1] = -1e30f;
                    if (c0i > r1 || c0i >= len) sc[nf][2] = -1e30f;
                    if (c1i > r1 || c1i >= len) sc[nf][3] = -1e30f;
                }
            }

            // Row max (fmax tree + 2-lane butterfly over the quad)
            float rm0 = -1e30f, rm1 = -1e30f;
            #pragma unroll
            for (int nf = 0; nf < 8; nf++) {
                rm0 = fmaxf(rm0, fmaxf(sc[nf][0], sc[nf][1]));
                rm1 = fmaxf(rm1, fmaxf(sc[nf][2], sc[nf][3]));
            }
            rm0 = fmaxf(rm0, __shfl_xor_sync(0xffffffffu, rm0, 1));
            rm0 = fmaxf(rm0, __shfl_xor_sync(0xffffffffu, rm0, 2));
            rm1 = fmaxf(rm1, __shfl_xor_sync(0xffffffffu, rm1, 1));
            rm1 = fmaxf(rm1, __shfl_xor_sync(0xffffffffu, rm1, 2));

            float mn0 = fmaxf(m0, rm0), mn1 = fmaxf(m1, rm1);
            float al0 = exp2f(m0 - mn0), al1 = exp2f(m1 - mn1);
            m0 = mn0; m1 = mn1;

            // Rescale accumulators (incl. row-sum column)
            #pragma unroll
            for (int nf = 0; nf < 8; nf++) {
                oc[nf][0] *= al0; oc[nf][1] *= al0;
                oc[nf][2] *= al1; oc[nf][3] *= al1;
            }
            ol[0] *= al0; ol[1] *= al0; ol[2] *= al1; ol[3] *= al1;

            // P = exp2(S - m) directly in fp16 (packed), then PV + row-sum MMA
            #pragma unroll
            for (int kk = 0; kk < 4; kk++) {
                unsigned pa[4];
                pa[0] = ex2h2(h2bits(sc[2 * kk][0] - mn0,     sc[2 * kk][1] - mn0));
                pa[1] = ex2h2(h2bits(sc[2 * kk][2] - mn1,     sc[2 * kk][3] - mn1));
                pa[2] = ex2h2(h2bits(sc[2 * kk + 1][0] - mn0, sc[2 * kk + 1][1] - mn0));
                pa[3] = ex2h2(h2bits(sc[2 * kk + 1][2] - mn1, sc[2 * kk + 1][3] - mn1));
                #pragma unroll
                for (int np = 0; np < 4; np++) {
                    unsigned v0, v1, v2, v3;
                    unsigned addr = smaddr(&Vb[(kk * 16 + vrow) * AST + np * 16 + vcol]);
                    LDM_X4T(v0, v1, v2, v3, addr);
                    mma16(oc[2 * np],     pa, v0, v1);
                    mma16(oc[2 * np + 1], pa, v2, v3);
                }
                mma16(ol, pa, HONES, HONES);   // row sums, no smem
            }
        }
        __syncthreads();
    }

    // Epilogue: normalize by the MMA-accumulated row sums, write O (half)
    float inv0 = 1.0f / ol[0], inv1 = 1.0f / ol[2];
    __half* Og = g_Oh + ((size_t)(n * L_ + row_w)) * D_ + h * DK_;
    #pragma unroll
    for (int nf = 0; nf < 8; nf++) {
        int cb = nf * 8 + 2 * t;
        *(unsigned*)(Og + (size_t)g * D_ + cb) =
            h2bits(oc[nf][0] * inv0, oc[nf][1] * inv0);
        *(unsigned*)(Og + (size_t)(g + 8) * D_ + cb) =
            h2bits(oc[nf][2] * inv1, oc[nf][3] * inv1);
    }
}

// ---------------------------------------------------------------------------
extern "C" void kernel_launch(void* const* d_in, const int* in_sizes, int n_in,
                              void* d_out, int out_size)
{
    const float* x_q = (const float*)d_in[0];
    const float* x_k = (const float*)d_in[1];
    const float* x_v = (const float*)d_in[2];
    const int*   pm  = (const int*)  d_in[3];
    // d_in[4] = attention_mask (causal) — handled analytically
    const float* Wq = (const float*)d_in[5];
    const float* bq = (const float*)d_in[6];
    const float* Wk = (const float*)d_in[7];
    const float* bk = (const float*)d_in[8];
    const float* Wv = (const float*)d_in[9];
    const float* bv = (const float*)d_in[10];
    const float* Wo = (const float*)d_in[11];
    const float* bo = (const float*)d_in[12];
    float* out = (float*)d_out;

    __half *xqh, *xkh, *xvh, *wqh, *wkh, *wvh, *woh, *Qh, *Kh, *Vh, *Oh;
    cudaGetSymbolAddress((void**)&xqh, g_xqh);
    cudaGetSymbolAddress((void**)&xkh, g_xkh);
    cudaGetSymbolAddress((void**)&xvh, g_xvh);
    cudaGetSymbolAddress((void**)&wqh, g_wqh);
    cudaGetSymbolAddress((void**)&wkh, g_wkh);
    cudaGetSymbolAddress((void**)&wvh, g_wvh);
    cudaGetSymbolAddress((void**)&woh, g_woh);
    cudaGetSymbolAddress((void**)&Qh,  g_Qh);
    cudaGetSymbolAddress((void**)&Kh,  g_Kh);
    cudaGetSymbolAddress((void**)&Vh,  g_Vh);
    cudaGetSymbolAddress((void**)&Oh,  g_Oh);

    cudaFuncSetAttribute(gemm_qkv, cudaFuncAttributeMaxDynamicSharedMemorySize,
                         GEMM_SMEM);
    cudaFuncSetAttribute(gemm_o, cudaFuncAttributeMaxDynamicSharedMemorySize,
                         GEMM_SMEM);
    cudaFuncSetAttribute(attn_h, cudaFuncAttributeMaxDynamicSharedMemorySize,
                         ATTN_SMEM);

    len_kernel<<<N_, 256>>>(pm);

    const int X4 = M_ * D_ / 4;   // 1,048,576
    const int W4 = D_ * D_ / 4;   // 65,536
    cvt3_kernel<<<dim3(X4 / 512, 3), 256>>>(
        (const float4*)x_q, (const float4*)x_k, (const float4*)x_v,
        (uint2*)xqh, (uint2*)xkh, (uint2*)xvh, X4);
    cvt4_kernel<<<dim3(W4 / 512, 4), 256>>>(
        (const float4*)Wq, (const float4*)Wk, (const float4*)Wv, (const float4*)Wo,
        (uint2*)wqh, (uint2*)wkh, (uint2*)wvh, (uint2*)woh, W4);

    gemm_qkv<<<dim3(M_ / 128, D_ / 128, 3), 256, GEMM_SMEM>>>(
        xqh, xkh, xvh, wqh, wkh, wvh, bq, bk, bv, Qh, Kh, Vh);

    attn_h<<<dim3(L_ / 128, H_, N_), 256, ATTN_SMEM>>>(0);

    gemm_o<<<dim3(M_ / 128, D_ / 128), 256, GEMM_SMEM>>>(Oh, woh, bo, out);
}